// round 14
// baseline (speedup 1.0000x reference)
#include <cuda_runtime.h>
#include <cuda_fp16.h>
#include <cstdint>

// B=8, in=64, out=64, P=192*192=36864, G=6, K=64*6=384
// R8 structure (best known): 2 CTAs/SM, 128 threads, M-tile 64, 12 of 24
// B k-steps register-cached. R14: hat weights via FADD.SAT (saturate trick)
// -- removes one FMNMX per weight, ~22% of build issue slots.
#define IND   64
#define OUTD  64
#define PTOT  36864
#define MT    64            // pixel tile (M)
#define TPC   16            // tiles per CTA
#define NSTEP 24            // K/16 = 384/16
#define NCACH 12            // B k-steps held in registers
#define NLD   (NSTEP - NCACH)
#define TILES_PER_B 36      // (36864/64)/TPC

#define ROWB  768           // bytes per K-row (384 fp16)
#define A_OFF   0
#define A_BYTES (MT * ROWB)       // 49152
#define B_OFF   A_BYTES
#define B_BYTES (OUTD * ROWB)     // 49152
#define SMEM_TOTAL (A_BYTES + B_BYTES)   // 98304

__device__ __forceinline__ uint32_t smem_u32(const void* p) {
    uint32_t a;
    asm("{ .reg .u64 t; cvta.to.shared.u64 t, %1; cvt.u32.u64 %0, t; }"
        : "=r"(a) : "l"(p));
    return a;
}
__device__ __forceinline__ uint32_t pack2(float a, float b) {
    __half2 h = __floats2half2_rn(a, b);
    return *reinterpret_cast<uint32_t*>(&h);
}
__device__ __forceinline__ void mma16816(float* c, const uint32_t* a,
                                         const uint32_t* b) {
    asm volatile(
        "mma.sync.aligned.m16n8k16.row.col.f32.f16.f16.f32 "
        "{%0,%1,%2,%3}, {%4,%5,%6,%7}, {%8,%9}, {%0,%1,%2,%3};"
        : "+f"(c[0]), "+f"(c[1]), "+f"(c[2]), "+f"(c[3])
        : "r"(a[0]), "r"(a[1]), "r"(a[2]), "r"(a[3]), "r"(b[0]), "r"(b[1]));
}
__device__ __forceinline__ void ldsm_x4(uint32_t* r, uint32_t addr) {
    asm volatile(
        "ldmatrix.sync.aligned.m8n8.x4.shared.b16 {%0,%1,%2,%3}, [%4];"
        : "=r"(r[0]), "=r"(r[1]), "=r"(r[2]), "=r"(r[3]) : "r"(addr));
}

// hat weight: 1-|nx-g| <= 1 always, so max(0,.) == saturate(.) -> FADD.SAT
__device__ __forceinline__ float hatw(float nx, float g) {
    return __saturatef(1.0f - fabsf(nx - g));
}

// swizzle: 16B-chunk index XORed with S(row); S(row)=(row&7)^(((row>>5)&1)<<2)
__device__ __forceinline__ uint32_t srow(int row) {
    return (uint32_t)((row & 7) ^ (((row >> 5) & 1) << 2));
}

__global__ void __launch_bounds__(128, 2)
bspline_kernel(const float* __restrict__ x, const float* __restrict__ coef,
               float* __restrict__ out) {
    extern __shared__ __align__(16) char smem[];
    const uint32_t sbase = smem_u32(smem);
    const int tid = threadIdx.x;
    const int wid = tid >> 5;
    const int lid = tid & 31;

    const int b = blockIdx.x / TILES_PER_B;
    const int tile0 = (blockIdx.x % TILES_PER_B) * TPC;

    // ---- Stage coef[b] -> SMEM B fp16 ----
    {
        const float* cb = coef + (size_t)b * OUTD * IND * 6;
        #pragma unroll
        for (int j = 0; j < 32; j++) {
            int pr = j * 128 + tid;            // pr = o*64 + i
            int o = pr >> 6, i = pr & 63;
            const float2* cp = (const float2*)(cb + (size_t)pr * 6);
            float2 c01 = cp[0], c23 = cp[1], c45 = cp[2];
            uint32_t sw = srow(o) << 4;
            char* rowp = smem + B_OFF + o * ROWB;
            uint32_t d0 = (uint32_t)(i * 12);
            *(uint32_t*)(rowp + ((d0     ) ^ sw)) = pack2(c01.x, c01.y);
            *(uint32_t*)(rowp + ((d0 + 4 ) ^ sw)) = pack2(c23.x, c23.y);
            *(uint32_t*)(rowp + ((d0 + 8 ) ^ sw)) = pack2(c45.x, c45.y);
        }
    }

    // A-build mapping: i = tid/2, pixel half q = tid&1 (32 pixels each)
    const int ai = tid >> 1;
    const int aq = tid & 1;
    const float4* xbase = (const float4*)(x + (size_t)(b * IND + ai) * PTOT
                                          + aq * 32);

    // mainloop lane constants: 4 warps, warp tile m32 x n32
    const int warp_m = wid & 1;
    const int warp_n = wid >> 1;
    const int q   = lid >> 3;
    const int rlo = lid & 7;
    const uint32_t ca = (uint32_t)(q >> 1);
    const uint32_t SaX = (uint32_t)(rlo ^ ((warp_m & 1) << 2));
    uint32_t rbA[2];
    #pragma unroll
    for (int mf = 0; mf < 2; mf++)
        rbA[mf] = sbase + A_OFF +
                  (uint32_t)(warp_m * 32 + mf * 16 + (q & 1) * 8 + rlo) * ROWB;
    const uint32_t SbX = (uint32_t)(rlo ^ ((warp_n & 1) << 2));
    uint32_t rbB[2];
    #pragma unroll
    for (int g = 0; g < 2; g++)
        rbB[g] = sbase + B_OFF +
                 (uint32_t)(warp_n * 32 + g * 16 + (q & 1) * 8 + rlo) * ROWB;

    // ---- Prologue: load x for tile 0 ----
    float4 cur[8];
    {
        const float4* xp4 = xbase + (size_t)(tile0 * MT) / 4;
        #pragma unroll
        for (int j = 0; j < 8; j++) cur[j] = xp4[j];
    }

    // ---- Wait for B staged, then cache k-steps 12..23 of B in registers ----
    __syncthreads();
    uint32_t bc[NCACH][8];
    #pragma unroll
    for (int s = 0; s < NCACH; s++) {
        const uint32_t c = (uint32_t)(2 * (s + NLD)) + ca;
        ldsm_x4(&bc[s][0], rbB[0] + ((c ^ SbX) << 4));
        ldsm_x4(&bc[s][4], rbB[1] + ((c ^ SbX) << 4));
    }

    for (int t = 0; t < TPC; t++) {
        const int p0 = (tile0 + t) * MT;
        if (t) __syncthreads();   // prior MMA reads of A done before overwrite

        // ---- Build A tile from registers: hat weights (FADD.SAT form) ----
        #pragma unroll
        for (int j = 0; j < 8; j++) {
            float vv[4] = {cur[j].x, cur[j].y, cur[j].z, cur[j].w};
            #pragma unroll
            for (int e = 0; e < 4; e++) {
                int p = aq * 32 + j * 4 + e;
                float xc = fminf(fmaxf(vv[e], -1.0f), 1.0f);
                float nx = fmaf(xc, 2.5f, 2.5f);
                float w0 = hatw(nx, 0.0f);
                float w1 = hatw(nx, 1.0f);
                float w2 = hatw(nx, 2.0f);
                float w3 = hatw(nx, 3.0f);
                float w4 = hatw(nx, 4.0f);
                float w5 = hatw(nx, 5.0f);
                uint32_t sw = srow(p) << 4;
                char* rowp = smem + A_OFF + p * ROWB;
                uint32_t d0 = (uint32_t)(ai * 12);
                *(uint32_t*)(rowp + ((d0     ) ^ sw)) = pack2(w0, w1);
                *(uint32_t*)(rowp + ((d0 + 4 ) ^ sw)) = pack2(w2, w3);
                *(uint32_t*)(rowp + ((d0 + 8 ) ^ sw)) = pack2(w4, w5);
            }
        }

        // cur dead now: start loading next tile's x (hidden by mainloop)
        if (t + 1 < TPC) {
            const float4* xp4 = xbase + (size_t)(p0 + MT) / 4;
            #pragma unroll
            for (int j = 0; j < 8; j++) cur[j] = xp4[j];
        }
        __syncthreads();

        // ---- Mainloop: D[64x64] += A[64x384] * B[64x384]^T ----
        float acc[2][4][4];
        #pragma unroll
        for (int mf = 0; mf < 2; mf++)
            #pragma unroll
            for (int nf = 0; nf < 4; nf++)
                #pragma unroll
                for (int e = 0; e < 4; e++) acc[mf][nf][e] = 0.0f;

        #pragma unroll
        for (int s = 0; s < NSTEP; s++) {
            const uint32_t c = (uint32_t)(2 * s) + ca;
            uint32_t af[2][4], bf[2][4];
            ldsm_x4(af[0], rbA[0] + ((c ^ SaX) << 4));
            ldsm_x4(af[1], rbA[1] + ((c ^ SaX) << 4));
            if (s < NLD) {
                ldsm_x4(bf[0], rbB[0] + ((c ^ SbX) << 4));
                ldsm_x4(bf[1], rbB[1] + ((c ^ SbX) << 4));
            } else {
                #pragma unroll
                for (int j = 0; j < 4; j++) {
                    bf[0][j] = bc[s - NLD][j];
                    bf[1][j] = bc[s - NLD][4 + j];
                }
            }
            #pragma unroll
            for (int g = 0; g < 2; g++) {
                uint32_t b0[2] = {bf[g][0], bf[g][2]};   // nf = g*2
                uint32_t b1[2] = {bf[g][1], bf[g][3]};   // nf = g*2+1
                mma16816(acc[0][g * 2    ], af[0], b0);
                mma16816(acc[1][g * 2    ], af[1], b0);
                mma16816(acc[0][g * 2 + 1], af[0], b1);
                mma16816(acc[1][g * 2 + 1], af[1], b1);
            }
        }

        // ---- Epilogue: direct STG (32B-sector coalesced per o-row) ----
        const int lr = lid >> 2;
        #pragma unroll
        for (int mf = 0; mf < 2; mf++) {
            int row = warp_m * 32 + mf * 16 + lr;
            #pragma unroll
            for (int g = 0; g < 2; g++) {
                #pragma unroll
                for (int h = 0; h < 2; h++) {
                    int nf = g * 2 + h;
                    int o = warp_n * 32 + g * 16 + h * 8 + ((lid & 3) << 1);
                    float* op = out + (size_t)(b * OUTD + o) * PTOT + p0 + row;
                    op[0]        = acc[mf][nf][0];
                    op[PTOT]     = acc[mf][nf][1];
                    op[8]        = acc[mf][nf][2];
                    op[PTOT + 8] = acc[mf][nf][3];
                }
            }
        }
    }
}

extern "C" void kernel_launch(void* const* d_in, const int* in_sizes, int n_in,
                              void* d_out, int out_size) {
    const float* x    = (const float*)d_in[0];
    const float* coef = (const float*)d_in[1];
    float* out = (float*)d_out;
    (void)in_sizes; (void)n_in; (void)out_size;

    cudaFuncSetAttribute(bspline_kernel,
                         cudaFuncAttributeMaxDynamicSharedMemorySize, SMEM_TOTAL);
    bspline_kernel<<<8 * TILES_PER_B, 128, SMEM_TOTAL>>>(x, coef, out);
}

// round 15
// speedup vs baseline: 1.5232x; 1.5232x over previous
#include <cuda_runtime.h>
#include <cuda_fp16.h>
#include <cstdint>

// B=8, in=64, out=64, P=192*192=36864, G=6, K=64*6=384
// R8 structure (best known): 2 CTAs/SM, 128 threads, M-tile 64, 12 of 24
// B k-steps register-cached, x prefetch after build. R15: edge hat weights
// simplified (nx in [0,5] -> w0=max(0,1-nx), w5=max(0,nx-4)); all ops stay
// on fma/alu pipes (the R14 __saturatef/F2F.SAT regression is reverted).
#define IND   64
#define OUTD  64
#define PTOT  36864
#define MT    64            // pixel tile (M)
#define TPC   16            // tiles per CTA
#define NSTEP 24            // K/16 = 384/16
#define NCACH 12            // B k-steps held in registers
#define NLD   (NSTEP - NCACH)
#define TILES_PER_B 36      // (36864/64)/TPC

#define ROWB  768           // bytes per K-row (384 fp16)
#define A_OFF   0
#define A_BYTES (MT * ROWB)       // 49152
#define B_OFF   A_BYTES
#define B_BYTES (OUTD * ROWB)     // 49152
#define SMEM_TOTAL (A_BYTES + B_BYTES)   // 98304

__device__ __forceinline__ uint32_t smem_u32(const void* p) {
    uint32_t a;
    asm("{ .reg .u64 t; cvta.to.shared.u64 t, %1; cvt.u32.u64 %0, t; }"
        : "=r"(a) : "l"(p));
    return a;
}
__device__ __forceinline__ uint32_t pack2(float a, float b) {
    __half2 h = __floats2half2_rn(a, b);
    return *reinterpret_cast<uint32_t*>(&h);
}
__device__ __forceinline__ void mma16816(float* c, const uint32_t* a,
                                         const uint32_t* b) {
    asm volatile(
        "mma.sync.aligned.m16n8k16.row.col.f32.f16.f16.f32 "
        "{%0,%1,%2,%3}, {%4,%5,%6,%7}, {%8,%9}, {%0,%1,%2,%3};"
        : "+f"(c[0]), "+f"(c[1]), "+f"(c[2]), "+f"(c[3])
        : "r"(a[0]), "r"(a[1]), "r"(a[2]), "r"(a[3]), "r"(b[0]), "r"(b[1]));
}
__device__ __forceinline__ void ldsm_x4(uint32_t* r, uint32_t addr) {
    asm volatile(
        "ldmatrix.sync.aligned.m8n8.x4.shared.b16 {%0,%1,%2,%3}, [%4];"
        : "=r"(r[0]), "=r"(r[1]), "=r"(r[2]), "=r"(r[3]) : "r"(addr));
}

// swizzle: 16B-chunk index XORed with S(row); S(row)=(row&7)^(((row>>5)&1)<<2)
__device__ __forceinline__ uint32_t srow(int row) {
    return (uint32_t)((row & 7) ^ (((row >> 5) & 1) << 2));
}

__global__ void __launch_bounds__(128, 2)
bspline_kernel(const float* __restrict__ x, const float* __restrict__ coef,
               float* __restrict__ out) {
    extern __shared__ __align__(16) char smem[];
    const uint32_t sbase = smem_u32(smem);
    const int tid = threadIdx.x;
    const int wid = tid >> 5;
    const int lid = tid & 31;

    const int b = blockIdx.x / TILES_PER_B;
    const int tile0 = (blockIdx.x % TILES_PER_B) * TPC;

    // ---- Stage coef[b] -> SMEM B fp16 ----
    {
        const float* cb = coef + (size_t)b * OUTD * IND * 6;
        #pragma unroll
        for (int j = 0; j < 32; j++) {
            int pr = j * 128 + tid;            // pr = o*64 + i
            int o = pr >> 6, i = pr & 63;
            const float2* cp = (const float2*)(cb + (size_t)pr * 6);
            float2 c01 = cp[0], c23 = cp[1], c45 = cp[2];
            uint32_t sw = srow(o) << 4;
            char* rowp = smem + B_OFF + o * ROWB;
            uint32_t d0 = (uint32_t)(i * 12);
            *(uint32_t*)(rowp + ((d0     ) ^ sw)) = pack2(c01.x, c01.y);
            *(uint32_t*)(rowp + ((d0 + 4 ) ^ sw)) = pack2(c23.x, c23.y);
            *(uint32_t*)(rowp + ((d0 + 8 ) ^ sw)) = pack2(c45.x, c45.y);
        }
    }

    // A-build mapping: i = tid/2, pixel half q = tid&1 (32 pixels each)
    const int ai = tid >> 1;
    const int aq = tid & 1;
    const float4* xbase = (const float4*)(x + (size_t)(b * IND + ai) * PTOT
                                          + aq * 32);

    // mainloop lane constants: 4 warps, warp tile m32 x n32
    const int warp_m = wid & 1;
    const int warp_n = wid >> 1;
    const int q   = lid >> 3;
    const int rlo = lid & 7;
    const uint32_t ca = (uint32_t)(q >> 1);
    const uint32_t SaX = (uint32_t)(rlo ^ ((warp_m & 1) << 2));
    uint32_t rbA[2];
    #pragma unroll
    for (int mf = 0; mf < 2; mf++)
        rbA[mf] = sbase + A_OFF +
                  (uint32_t)(warp_m * 32 + mf * 16 + (q & 1) * 8 + rlo) * ROWB;
    const uint32_t SbX = (uint32_t)(rlo ^ ((warp_n & 1) << 2));
    uint32_t rbB[2];
    #pragma unroll
    for (int g = 0; g < 2; g++)
        rbB[g] = sbase + B_OFF +
                 (uint32_t)(warp_n * 32 + g * 16 + (q & 1) * 8 + rlo) * ROWB;

    // ---- Prologue: load x for tile 0 ----
    float4 cur[8];
    {
        const float4* xp4 = xbase + (size_t)(tile0 * MT) / 4;
        #pragma unroll
        for (int j = 0; j < 8; j++) cur[j] = xp4[j];
    }

    // ---- Wait for B staged, then cache k-steps 12..23 of B in registers ----
    __syncthreads();
    uint32_t bc[NCACH][8];
    #pragma unroll
    for (int s = 0; s < NCACH; s++) {
        const uint32_t c = (uint32_t)(2 * (s + NLD)) + ca;
        ldsm_x4(&bc[s][0], rbB[0] + ((c ^ SbX) << 4));
        ldsm_x4(&bc[s][4], rbB[1] + ((c ^ SbX) << 4));
    }

    for (int t = 0; t < TPC; t++) {
        const int p0 = (tile0 + t) * MT;
        if (t) __syncthreads();   // prior MMA reads of A done before overwrite

        // ---- Build A tile from registers: hat weights ----
        #pragma unroll
        for (int j = 0; j < 8; j++) {
            float vv[4] = {cur[j].x, cur[j].y, cur[j].z, cur[j].w};
            #pragma unroll
            for (int e = 0; e < 4; e++) {
                int p = aq * 32 + j * 4 + e;
                float xc = fminf(fmaxf(vv[e], -1.0f), 1.0f);
                float nx = fmaf(xc, 2.5f, 2.5f);      // in [0, 5]
                float w0 = fmaxf(0.0f, 1.0f - nx);            // |nx-0| = nx
                float w1 = fmaxf(0.0f, 1.0f - fabsf(nx - 1.0f));
                float w2 = fmaxf(0.0f, 1.0f - fabsf(nx - 2.0f));
                float w3 = fmaxf(0.0f, 1.0f - fabsf(nx - 3.0f));
                float w4 = fmaxf(0.0f, 1.0f - fabsf(nx - 4.0f));
                float w5 = fmaxf(0.0f, nx - 4.0f);            // 1-|nx-5| = nx-4
                uint32_t sw = srow(p) << 4;
                char* rowp = smem + A_OFF + p * ROWB;
                uint32_t d0 = (uint32_t)(ai * 12);
                *(uint32_t*)(rowp + ((d0     ) ^ sw)) = pack2(w0, w1);
                *(uint32_t*)(rowp + ((d0 + 4 ) ^ sw)) = pack2(w2, w3);
                *(uint32_t*)(rowp + ((d0 + 8 ) ^ sw)) = pack2(w4, w5);
            }
        }

        // cur dead now: start loading next tile's x (hidden by mainloop)
        if (t + 1 < TPC) {
            const float4* xp4 = xbase + (size_t)(p0 + MT) / 4;
            #pragma unroll
            for (int j = 0; j < 8; j++) cur[j] = xp4[j];
        }
        __syncthreads();

        // ---- Mainloop: D[64x64] += A[64x384] * B[64x384]^T ----
        float acc[2][4][4];
        #pragma unroll
        for (int mf = 0; mf < 2; mf++)
            #pragma unroll
            for (int nf = 0; nf < 4; nf++)
                #pragma unroll
                for (int e = 0; e < 4; e++) acc[mf][nf][e] = 0.0f;

        #pragma unroll
        for (int s = 0; s < NSTEP; s++) {
            const uint32_t c = (uint32_t)(2 * s) + ca;
            uint32_t af[2][4], bf[2][4];
            ldsm_x4(af[0], rbA[0] + ((c ^ SaX) << 4));
            ldsm_x4(af[1], rbA[1] + ((c ^ SaX) << 4));
            if (s < NLD) {
                ldsm_x4(bf[0], rbB[0] + ((c ^ SbX) << 4));
                ldsm_x4(bf[1], rbB[1] + ((c ^ SbX) << 4));
            } else {
                #pragma unroll
                for (int j = 0; j < 4; j++) {
                    bf[0][j] = bc[s - NLD][j];
                    bf[1][j] = bc[s - NLD][4 + j];
                }
            }
            #pragma unroll
            for (int g = 0; g < 2; g++) {
                uint32_t b0[2] = {bf[g][0], bf[g][2]};   // nf = g*2
                uint32_t b1[2] = {bf[g][1], bf[g][3]};   // nf = g*2+1
                mma16816(acc[0][g * 2    ], af[0], b0);
                mma16816(acc[1][g * 2    ], af[1], b0);
                mma16816(acc[0][g * 2 + 1], af[0], b1);
                mma16816(acc[1][g * 2 + 1], af[1], b1);
            }
        }

        // ---- Epilogue: direct STG (32B-sector coalesced per o-row) ----
        const int lr = lid >> 2;
        #pragma unroll
        for (int mf = 0; mf < 2; mf++) {
            int row = warp_m * 32 + mf * 16 + lr;
            #pragma unroll
            for (int g = 0; g < 2; g++) {
                #pragma unroll
                for (int h = 0; h < 2; h++) {
                    int nf = g * 2 + h;
                    int o = warp_n * 32 + g * 16 + h * 8 + ((lid & 3) << 1);
                    float* op = out + (size_t)(b * OUTD + o) * PTOT + p0 + row;
                    op[0]        = acc[mf][nf][0];
                    op[PTOT]     = acc[mf][nf][1];
                    op[8]        = acc[mf][nf][2];
                    op[PTOT + 8] = acc[mf][nf][3];
                }
            }
        }
    }
}

extern "C" void kernel_launch(void* const* d_in, const int* in_sizes, int n_in,
                              void* d_out, int out_size) {
    const float* x    = (const float*)d_in[0];
    const float* coef = (const float*)d_in[1];
    float* out = (float*)d_out;
    (void)in_sizes; (void)n_in; (void)out_size;

    cudaFuncSetAttribute(bspline_kernel,
                         cudaFuncAttributeMaxDynamicSharedMemorySize, SMEM_TOTAL);
    bspline_kernel<<<8 * TILES_PER_B, 128, SMEM_TOTAL>>>(x, coef, out);
}